// round 2
// baseline (speedup 1.0000x reference)
#include <cuda_runtime.h>
#include <cstdint>

#define N_NODES 50000
#define N_EDGES 320000
#define MAXD    2048

// ---------------- static scratch (no allocations allowed) ----------------
__device__ float g_buf0[(size_t)N_NODES * MAXD];   // layer activations (ping)
__device__ float g_buf1[(size_t)N_NODES * MAXD];   // layer activations (pong)
__device__ float g_tmp [(size_t)N_NODES * MAXD];   // GEMM output before aggregation

__device__ int   g_deg[N_NODES];
__device__ float g_dinv[N_NODES];
__device__ int   g_rowptr[N_NODES + 1];
__device__ int   g_fill[N_NODES];
__device__ int   g_csr[N_EDGES];
__device__ int   g_is64;

// ---------------- index dtype handling ----------------
// Reference asks for int64 but JAX without x64 silently emits int32.
// If int64 (little-endian), every odd 32-bit word is a high word == 0
// (indices are in [0, 50000)). Sample 32 odd words; all zero => int64.
__global__ void detect_idx_kernel(const void* e) {
    const int* w = (const int*)e;
    int all0 = 1;
    for (int i = 1; i < 64; i += 2)
        if (w[i] != 0) all0 = 0;
    g_is64 = all0;
}

__device__ __forceinline__ int get_idx(const void* e, long long i) {
    if (g_is64) return (int)((const long long*)e)[i];
    return ((const int*)e)[i];
}

// ---------------- graph preprocessing ----------------
__global__ void zero_deg_kernel() {
    int i = blockIdx.x * blockDim.x + threadIdx.x;
    if (i < N_NODES) g_deg[i] = 0;
}

__global__ void count_deg_kernel(const void* e) {
    int i = blockIdx.x * blockDim.x + threadIdx.x;
    if (i >= N_EDGES) return;
    int dst = get_idx(e, (long long)N_EDGES + i);
    atomicAdd(&g_deg[dst], 1);
}

// single-block exclusive scan over degrees; also computes dinv
__global__ void scan_kernel() {
    __shared__ int s[1024];
    __shared__ int carry;
    if (threadIdx.x == 0) carry = 0;
    __syncthreads();
    for (int base = 0; base < N_NODES; base += 1024) {
        int i = base + threadIdx.x;
        int v = (i < N_NODES) ? g_deg[i] : 0;
        s[threadIdx.x] = v;
        __syncthreads();
        for (int off = 1; off < 1024; off <<= 1) {
            int t = (threadIdx.x >= off) ? s[threadIdx.x - off] : 0;
            __syncthreads();
            s[threadIdx.x] += t;
            __syncthreads();
        }
        int incl = s[threadIdx.x];
        int excl = incl - v;
        if (i < N_NODES) {
            g_rowptr[i] = carry + excl;
            g_fill[i]   = carry + excl;
            g_dinv[i]   = rsqrtf((float)v + 1.0f);
        }
        __syncthreads();
        if (threadIdx.x == 1023) carry += incl;
        __syncthreads();
    }
    if (threadIdx.x == 0) g_rowptr[N_NODES] = carry;
}

__global__ void fill_csr_kernel(const void* e) {
    int i = blockIdx.x * blockDim.x + threadIdx.x;
    if (i >= N_EDGES) return;
    int src = get_idx(e, i);
    int dst = get_idx(e, (long long)N_EDGES + i);
    int pos = atomicAdd(&g_fill[dst], 1);
    g_csr[pos] = src;
}

// ---------------- fp32 SGEMM: C[M,N] = A[M,K] @ B[K,N] ----------------
// BM=BN=128, BK=8, 256 threads, 8x8 micro-tile per thread.
__global__ void __launch_bounds__(256, 2)
sgemm_kernel(const float* __restrict__ A, const float* __restrict__ B,
             float* __restrict__ C, int M, int N, int K) {
    __shared__ float As[8][128];
    __shared__ float Bs[8][128];

    int tid = threadIdx.x;
    int bm  = blockIdx.y * 128;
    int bn  = blockIdx.x * 128;
    int tx  = tid & 15;   // n direction
    int ty  = tid >> 4;   // m direction

    float acc[8][8];
#pragma unroll
    for (int i = 0; i < 8; i++)
#pragma unroll
        for (int j = 0; j < 8; j++) acc[i][j] = 0.f;

    int aRow = tid >> 1;
    int aCol = (tid & 1) << 2;
    int bRow = tid >> 5;
    int bCol = (tid & 31) << 2;

    const float* Ap = A + (size_t)(bm + aRow) * K + aCol;
    const float* Bp = B + (size_t)bRow * N + bn + bCol;
    bool aV = (bm + aRow) < M;

    for (int k0 = 0; k0 < K; k0 += 8) {
        float4 av = aV ? *(const float4*)Ap : make_float4(0.f, 0.f, 0.f, 0.f);
        float4 bv = *(const float4*)Bp;
        As[aCol + 0][aRow] = av.x;
        As[aCol + 1][aRow] = av.y;
        As[aCol + 2][aRow] = av.z;
        As[aCol + 3][aRow] = av.w;
        *(float4*)&Bs[bRow][bCol] = bv;
        __syncthreads();
#pragma unroll
        for (int k = 0; k < 8; k++) {
            float ar[8], br[8];
#pragma unroll
            for (int i = 0; i < 8; i++) ar[i] = As[k][ty * 8 + i];
#pragma unroll
            for (int j = 0; j < 8; j++) br[j] = Bs[k][tx * 8 + j];
#pragma unroll
            for (int i = 0; i < 8; i++)
#pragma unroll
                for (int j = 0; j < 8; j++) acc[i][j] += ar[i] * br[j];
        }
        __syncthreads();
        Ap += 8;
        Bp += (size_t)8 * N;
    }

#pragma unroll
    for (int i = 0; i < 8; i++) {
        int row = bm + ty * 8 + i;
        if (row < M) {
            float4* cp = (float4*)(C + (size_t)row * N + bn + tx * 8);
            cp[0] = make_float4(acc[i][0], acc[i][1], acc[i][2], acc[i][3]);
            cp[1] = make_float4(acc[i][4], acc[i][5], acc[i][6], acc[i][7]);
        }
    }
}

// ---------------- CSR aggregation ----------------
// out[n] = sum_{src in CSR[n]} tmp[src] * dinv[src]*dinv[n]
//        + tmp[n] * dinv[n]^2 + bias       (+ relu)
// one block (128 threads) per node; float4 columns.
__global__ void __launch_bounds__(128)
agg_kernel(const float* __restrict__ tmp, const float* __restrict__ bias,
           float* __restrict__ out, int d, int relu) {
    int node = blockIdx.x;
    int tid  = threadIdx.x;
    float di = g_dinv[node];
    int beg = g_rowptr[node];
    int end = g_rowptr[node + 1];
    int nc4 = d >> 2;

    float4 acc[4];
    float selfn = di * di;
    const float4* selfrow = (const float4*)(tmp + (size_t)node * d);
#pragma unroll
    for (int j = 0; j < 4; j++) {
        int c = tid + j * 128;
        if (c < nc4) {
            float4 v = selfrow[c];
            acc[j] = make_float4(v.x * selfn, v.y * selfn, v.z * selfn, v.w * selfn);
        } else {
            acc[j] = make_float4(0.f, 0.f, 0.f, 0.f);
        }
    }

    for (int e = beg; e < end; e++) {
        int src = g_csr[e];
        float nrm = di * g_dinv[src];
        const float4* row = (const float4*)(tmp + (size_t)src * d);
#pragma unroll
        for (int j = 0; j < 4; j++) {
            int c = tid + j * 128;
            if (c < nc4) {
                float4 v = row[c];
                acc[j].x += v.x * nrm;
                acc[j].y += v.y * nrm;
                acc[j].z += v.z * nrm;
                acc[j].w += v.w * nrm;
            }
        }
    }

    const float4* b4 = (const float4*)bias;
    float4* o = (float4*)(out + (size_t)node * d);
#pragma unroll
    for (int j = 0; j < 4; j++) {
        int c = tid + j * 128;
        if (c < nc4) {
            float4 bv = b4[c];
            float4 r = make_float4(acc[j].x + bv.x, acc[j].y + bv.y,
                                   acc[j].z + bv.z, acc[j].w + bv.w);
            if (relu) {
                r.x = fmaxf(r.x, 0.f);
                r.y = fmaxf(r.y, 0.f);
                r.z = fmaxf(r.z, 0.f);
                r.w = fmaxf(r.w, 0.f);
            }
            o[c] = r;
        }
    }
}

// ---------------- launch ----------------
extern "C" void kernel_launch(void* const* d_in, const int* in_sizes, int n_in,
                              void* d_out, int out_size) {
    const float* x = (const float*)d_in[0];
    const void*  e = d_in[1];
    const float* W[5] = {(const float*)d_in[2], (const float*)d_in[4],
                         (const float*)d_in[6], (const float*)d_in[8],
                         (const float*)d_in[10]};
    const float* b[5] = {(const float*)d_in[3], (const float*)d_in[5],
                         (const float*)d_in[7], (const float*)d_in[9],
                         (const float*)d_in[11]};
    float* out = (float*)d_out;

    float *h0, *h1, *tm;
    cudaGetSymbolAddress((void**)&h0, g_buf0);
    cudaGetSymbolAddress((void**)&h1, g_buf1);
    cudaGetSymbolAddress((void**)&tm, g_tmp);

    // graph preprocessing (every call — kernel_launch must be deterministic & self-contained)
    detect_idx_kernel<<<1, 1>>>(e);
    zero_deg_kernel<<<(N_NODES + 255) / 256, 256>>>();
    count_deg_kernel<<<(N_EDGES + 255) / 256, 256>>>(e);
    scan_kernel<<<1, 1024>>>();
    fill_csr_kernel<<<(N_EDGES + 255) / 256, 256>>>(e);

    const int dims[6] = {512, 2048, 1024, 512, 256, 128};
    const float* cur = x;
    float* bufs[2] = {h0, h1};

    for (int l = 0; l < 5; l++) {
        int K = dims[l];
        int N = dims[l + 1];
        dim3 grid(N / 128, (N_NODES + 127) / 128);
        sgemm_kernel<<<grid, 256>>>(cur, W[l], tm, N_NODES, N, K);
        float* dst = (l == 4) ? out : bufs[l & 1];
        agg_kernel<<<N_NODES, 128>>>(tm, b[l], dst, N, l < 4 ? 1 : 0);
        cur = dst;
    }
}

// round 4
// speedup vs baseline: 2.4725x; 2.4725x over previous
#include <cuda_runtime.h>
#include <cuda_bf16.h>
#include <cstdint>

#define N_NODES 50000
#define N_EDGES 320000
#define MAXD    2048
#define GSCAN   ((N_NODES + 1023) / 1024)

// ---------------- static scratch (no allocations allowed) ----------------
__device__ __nv_bfloat16 g_Ahi[(size_t)N_NODES * MAXD];   // activations hi
__device__ __nv_bfloat16 g_Alo[(size_t)N_NODES * MAXD];   // activations lo
__device__ float         g_tmp[(size_t)N_NODES * MAXD];   // GEMM output (pre-agg)
__device__ __nv_bfloat16 g_Whi[4 * 1024 * 1024];          // all transposed weights hi
__device__ __nv_bfloat16 g_Wlo[4 * 1024 * 1024];          // all transposed weights lo

__device__ int   g_deg[N_NODES];
__device__ float g_dinv[N_NODES];
__device__ int   g_rowptr[N_NODES + 1];
__device__ int   g_fill[N_NODES];
__device__ int   g_csr[N_EDGES];
__device__ int   g_bsum[64];
__device__ int   g_is64;

// ---------------- index dtype handling ----------------
__global__ void detect_idx_kernel(const void* e) {
    const int* w = (const int*)e;
    int all0 = 1;
    for (int i = 1; i < 64; i += 2)
        if (w[i] != 0) all0 = 0;
    g_is64 = all0;
}

__device__ __forceinline__ int get_idx(const void* e, long long i) {
    if (g_is64) return (int)((const long long*)e)[i];
    return ((const int*)e)[i];
}

// ---------------- graph preprocessing ----------------
__global__ void zero_deg_kernel() {
    int i = blockIdx.x * blockDim.x + threadIdx.x;
    if (i < N_NODES) g_deg[i] = 0;
}

__global__ void count_deg_kernel(const void* e) {
    int i = blockIdx.x * blockDim.x + threadIdx.x;
    if (i >= N_EDGES) return;
    int dst = get_idx(e, (long long)N_EDGES + i);
    atomicAdd(&g_deg[dst], 1);
}

// grid = GSCAN, block = 1024: per-block sums of degree chunks
__global__ void block_sum_kernel() {
    int i = blockIdx.x * 1024 + threadIdx.x;
    int v = (i < N_NODES) ? g_deg[i] : 0;
    int lane = threadIdx.x & 31, warp = threadIdx.x >> 5;
#pragma unroll
    for (int off = 16; off > 0; off >>= 1) v += __shfl_down_sync(0xffffffffu, v, off);
    __shared__ int ws[32];
    if (lane == 0) ws[warp] = v;
    __syncthreads();
    if (warp == 0) {
        int s = ws[lane];
#pragma unroll
        for (int off = 16; off > 0; off >>= 1) s += __shfl_down_sync(0xffffffffu, s, off);
        if (lane == 0) g_bsum[blockIdx.x] = s;
    }
}

__global__ void scan_partials_kernel() {
    int acc = 0;
    for (int i = 0; i < GSCAN; i++) { int t = g_bsum[i]; g_bsum[i] = acc; acc += t; }
    g_rowptr[N_NODES] = acc;
}

// grid = GSCAN, block = 1024: per-chunk exclusive scan + base, write rowptr/fill/dinv
__global__ void scatter_scan_kernel() {
    int i = blockIdx.x * 1024 + threadIdx.x;
    int v = (i < N_NODES) ? g_deg[i] : 0;
    int lane = threadIdx.x & 31, warp = threadIdx.x >> 5;
    int incl = v;
#pragma unroll
    for (int off = 1; off < 32; off <<= 1) {
        int t = __shfl_up_sync(0xffffffffu, incl, off);
        if (lane >= off) incl += t;
    }
    __shared__ int ws[32];
    if (lane == 31) ws[warp] = incl;
    __syncthreads();
    if (warp == 0) {
        int s = ws[lane];
#pragma unroll
        for (int off = 1; off < 32; off <<= 1) {
            int t = __shfl_up_sync(0xffffffffu, s, off);
            if (lane >= off) s += t;
        }
        ws[lane] = s;
    }
    __syncthreads();
    int wbase = (warp == 0) ? 0 : ws[warp - 1];
    int excl = g_bsum[blockIdx.x] + wbase + incl - v;
    if (i < N_NODES) {
        g_rowptr[i] = excl;
        g_fill[i]   = excl;
        g_dinv[i]   = rsqrtf((float)v + 1.0f);
    }
}

__global__ void fill_csr_kernel(const void* e) {
    int i = blockIdx.x * blockDim.x + threadIdx.x;
    if (i >= N_EDGES) return;
    int src = get_idx(e, i);
    int dst = get_idx(e, (long long)N_EDGES + i);
    int pos = atomicAdd(&g_fill[dst], 1);
    g_csr[pos] = src;
}

// ---------------- fp32 -> bf16 hi/lo conversions ----------------
__global__ void convert_x_kernel(const float* __restrict__ x, long long n) {
    long long i = (long long)blockIdx.x * blockDim.x + threadIdx.x;
    if (i >= n) return;
    float v = x[i];
    __nv_bfloat16 h = __float2bfloat16(v);
    g_Ahi[i] = h;
    g_Alo[i] = __float2bfloat16(v - __bfloat162float(h));
}

// W [K,N] row-major -> Wt [N,K] hi/lo at offset
__global__ void convert_w_kernel(const float* __restrict__ W, long long off, int K, int N) {
    int idx = blockIdx.x * blockDim.x + threadIdx.x;
    if (idx >= K * N) return;
    int k = idx / N, n = idx % N;
    float v = W[idx];
    __nv_bfloat16 h = __float2bfloat16(v);
    g_Whi[off + (size_t)n * K + k] = h;
    g_Wlo[off + (size_t)n * K + k] = __float2bfloat16(v - __bfloat162float(h));
}

// ---------------- bf16-split tensor-core GEMM ----------------
// C[M,N] = A[M,K] @ Wt[N,K]^T using acc += ahi*bhi + ahi*blo + alo*bhi
// 128x128x32 tiles, 256 threads (8 warps of 64x32), cp.async 2-stage,
// xor-swizzled smem + ldmatrix.x4, mma.sync.m16n8k16 bf16.
__device__ __forceinline__ void ldm4(uint32_t* r, uint32_t addr) {
    asm volatile("ldmatrix.sync.aligned.m8n8.x4.shared.b16 {%0,%1,%2,%3}, [%4];"
                 : "=r"(r[0]), "=r"(r[1]), "=r"(r[2]), "=r"(r[3]) : "r"(addr));
}

__device__ __forceinline__ void mma16816(float* c, const uint32_t* a, const uint32_t* b) {
    asm volatile(
        "mma.sync.aligned.m16n8k16.row.col.f32.bf16.bf16.f32 "
        "{%0,%1,%2,%3},{%4,%5,%6,%7},{%8,%9},{%0,%1,%2,%3};"
        : "+f"(c[0]), "+f"(c[1]), "+f"(c[2]), "+f"(c[3])
        : "r"(a[0]), "r"(a[1]), "r"(a[2]), "r"(a[3]), "r"(b[0]), "r"(b[1]));
}

__device__ __forceinline__ void cp16(uint32_t dst, const void* src, bool pred) {
    int sz = pred ? 16 : 0;
    asm volatile("cp.async.cg.shared.global [%0], [%1], 16, %2;\n"
                 :: "r"(dst), "l"(src), "r"(sz));
}

// tile layout: 128 rows x 32 k (bf16), swizzled: elem(row,k) = row*32 + ((k>>3)^((row>>1)&3))*8 + (k&7)
__device__ __forceinline__ void load_stage(
    uint32_t sbase, int stage,
    const __nv_bfloat16* __restrict__ Ahi, const __nv_bfloat16* __restrict__ Alo,
    const __nv_bfloat16* __restrict__ Bhi, const __nv_bfloat16* __restrict__ Blo,
    int bm, int bn, int k0, int M, int K, int tid)
{
    uint32_t st = sbase + stage * 32768;
#pragma unroll
    for (int h = 0; h < 2; h++) {
        int i = tid + h * 256;
        int row = i >> 2, chunk = i & 3;
        uint32_t doff = (uint32_t)(row * 32 + (chunk ^ ((row >> 1) & 3)) * 8) * 2;
        long arow = bm + row;
        bool av = arow < M;
        long arowc = av ? arow : 0;
        const __nv_bfloat16* pa = Ahi + (size_t)arowc * K + k0 + chunk * 8;
        const __nv_bfloat16* pal = Alo + (size_t)arowc * K + k0 + chunk * 8;
        const __nv_bfloat16* pb = Bhi + (size_t)(bn + row) * K + k0 + chunk * 8;
        const __nv_bfloat16* pbl = Blo + (size_t)(bn + row) * K + k0 + chunk * 8;
        cp16(st + 0 * 8192 + doff, pa, av);
        cp16(st + 1 * 8192 + doff, pal, av);
        cp16(st + 2 * 8192 + doff, pb, true);
        cp16(st + 3 * 8192 + doff, pbl, true);
    }
}

__global__ void __launch_bounds__(256)
bgemm_kernel(const __nv_bfloat16* __restrict__ Ahi, const __nv_bfloat16* __restrict__ Alo,
             const __nv_bfloat16* __restrict__ Bhi, const __nv_bfloat16* __restrict__ Blo,
             float* __restrict__ C, int M, int N, int K)
{
    extern __shared__ __align__(16) char smem[];
    uint32_t sbase = (uint32_t)__cvta_generic_to_shared(smem);

    int tid  = threadIdx.x;
    int lane = tid & 31, wid = tid >> 5;
    int wm = (wid >> 2) * 64;   // warp M offset in tile
    int wn = (wid & 3) * 32;    // warp N offset in tile
    int bm = blockIdx.y * 128;
    int bn = blockIdx.x * 128;

    float acc[4][4][4];
#pragma unroll
    for (int i = 0; i < 4; i++)
#pragma unroll
        for (int j = 0; j < 4; j++)
#pragma unroll
            for (int r = 0; r < 4; r++) acc[i][j][r] = 0.f;

    int nk = K >> 5;
    load_stage(sbase, 0, Ahi, Alo, Bhi, Blo, bm, bn, 0, M, K, tid);
    asm volatile("cp.async.commit_group;\n");

    int lr = lane & 15, lc = lane >> 4;

    for (int kt = 0; kt < nk; kt++) {
        if (kt + 1 < nk) {
            load_stage(sbase, (kt + 1) & 1, Ahi, Alo, Bhi, Blo, bm, bn, (kt + 1) * 32, M, K, tid);
            asm volatile("cp.async.commit_group;\n");
            asm volatile("cp.async.wait_group 1;\n");
        } else {
            asm volatile("cp.async.wait_group 0;\n");
        }
        __syncthreads();

        uint32_t st = sbase + (kt & 1) * 32768;
#pragma unroll
        for (int kk = 0; kk < 32; kk += 16) {
            int k = kk + lc * 8;
            uint32_t ah[4][4], al[4][4], bh[4][2], bl[4][2];
#pragma unroll
            for (int fm = 0; fm < 4; fm++) {
                int row = wm + fm * 16 + lr;
                uint32_t off = (uint32_t)(row * 32 + (((k >> 3) ^ ((row >> 1) & 3)) << 3)) * 2;
                ldm4(ah[fm], st + 0 * 8192 + off);
                ldm4(al[fm], st + 1 * 8192 + off);
            }
#pragma unroll
            for (int p = 0; p < 2; p++) {
                int row = wn + p * 16 + lr;
                uint32_t off = (uint32_t)(row * 32 + (((k >> 3) ^ ((row >> 1) & 3)) << 3)) * 2;
                uint32_t r[4];
                ldm4(r, st + 2 * 8192 + off);
                bh[p * 2][0] = r[0]; bh[p * 2][1] = r[2];
                bh[p * 2 + 1][0] = r[1]; bh[p * 2 + 1][1] = r[3];
                ldm4(r, st + 3 * 8192 + off);
                bl[p * 2][0] = r[0]; bl[p * 2][1] = r[2];
                bl[p * 2 + 1][0] = r[1]; bl[p * 2 + 1][1] = r[3];
            }
#pragma unroll
            for (int fm = 0; fm < 4; fm++)
#pragma unroll
                for (int fn = 0; fn < 4; fn++) {
                    mma16816(acc[fm][fn], ah[fm], bh[fn]);
                    mma16816(acc[fm][fn], ah[fm], bl[fn]);
                    mma16816(acc[fm][fn], al[fm], bh[fn]);
                }
        }
        __syncthreads();
    }

    int g = lane >> 2, tg = lane & 3;
#pragma unroll
    for (int fm = 0; fm < 4; fm++) {
#pragma unroll
        for (int fn = 0; fn < 4; fn++) {
            int row = bm + wm + fm * 16 + g;
            int col = bn + wn + fn * 8 + tg * 2;
            if (row < M)
                *(float2*)&C[(size_t)row * N + col] = make_float2(acc[fm][fn][0], acc[fm][fn][1]);
            if (row + 8 < M)
                *(float2*)&C[(size_t)(row + 8) * N + col] = make_float2(acc[fm][fn][2], acc[fm][fn][3]);
        }
    }
}

// ---------------- CSR aggregation (+bias, +relu, fused bf16 hi/lo out) ----------------
__global__ void __launch_bounds__(128)
agg_kernel(const float* __restrict__ tmp, const float* __restrict__ bias,
           float* __restrict__ outf, __nv_bfloat16* __restrict__ ahi,
           __nv_bfloat16* __restrict__ alo, int d, int last)
{
    int node = blockIdx.x;
    int tid  = threadIdx.x;
    float di = g_dinv[node];
    int beg = g_rowptr[node];
    int end = g_rowptr[node + 1];
    int nc4 = d >> 2;

    float4 acc[4];
    float selfn = di * di;
    const float4* selfrow = (const float4*)(tmp + (size_t)node * d);
#pragma unroll
    for (int j = 0; j < 4; j++) {
        int c = tid + j * 128;
        if (c < nc4) {
            float4 v = selfrow[c];
            acc[j] = make_float4(v.x * selfn, v.y * selfn, v.z * selfn, v.w * selfn);
        } else {
            acc[j] = make_float4(0.f, 0.f, 0.f, 0.f);
        }
    }

    for (int e = beg; e < end; e++) {
        int src = g_csr[e];
        float nrm = di * g_dinv[src];
        const float4* row = (const float4*)(tmp + (size_t)src * d);
#pragma unroll
        for (int j = 0; j < 4; j++) {
            int c = tid + j * 128;
            if (c < nc4) {
                float4 v = row[c];
                acc[j].x += v.x * nrm;
                acc[j].y += v.y * nrm;
                acc[j].z += v.z * nrm;
                acc[j].w += v.w * nrm;
            }
        }
    }

    const float4* b4 = (const float4*)bias;
#pragma unroll
    for (int j = 0; j < 4; j++) {
        int c = tid + j * 128;
        if (c >= nc4) continue;
        float4 bv = b4[c];
        float4 r = make_float4(acc[j].x + bv.x, acc[j].y + bv.y,
                               acc[j].z + bv.z, acc[j].w + bv.w);
        if (last) {
            ((float4*)(outf + (size_t)node * d))[c] = r;
        } else {
            r.x = fmaxf(r.x, 0.f); r.y = fmaxf(r.y, 0.f);
            r.z = fmaxf(r.z, 0.f); r.w = fmaxf(r.w, 0.f);
            __nv_bfloat16 h0 = __float2bfloat16(r.x);
            __nv_bfloat16 h1 = __float2bfloat16(r.y);
            __nv_bfloat16 h2 = __float2bfloat16(r.z);
            __nv_bfloat16 h3 = __float2bfloat16(r.w);
            __nv_bfloat162* dh = (__nv_bfloat162*)(ahi + (size_t)node * d);
            __nv_bfloat162* dl = (__nv_bfloat162*)(alo + (size_t)node * d);
            __nv_bfloat162 hh01; hh01.x = h0; hh01.y = h1;
            __nv_bfloat162 hh23; hh23.x = h2; hh23.y = h3;
            dh[2 * c]     = hh01;
            dh[2 * c + 1] = hh23;
            __nv_bfloat162 ll01, ll23;
            ll01.x = __float2bfloat16(r.x - __bfloat162float(h0));
            ll01.y = __float2bfloat16(r.y - __bfloat162float(h1));
            ll23.x = __float2bfloat16(r.z - __bfloat162float(h2));
            ll23.y = __float2bfloat16(r.w - __bfloat162float(h3));
            dl[2 * c]     = ll01;
            dl[2 * c + 1] = ll23;
        }
    }
}

// ---------------- launch ----------------
extern "C" void kernel_launch(void* const* d_in, const int* in_sizes, int n_in,
                              void* d_out, int out_size) {
    const float* x = (const float*)d_in[0];
    const void*  e = d_in[1];
    const float* W[5] = {(const float*)d_in[2], (const float*)d_in[4],
                         (const float*)d_in[6], (const float*)d_in[8],
                         (const float*)d_in[10]};
    const float* b[5] = {(const float*)d_in[3], (const float*)d_in[5],
                         (const float*)d_in[7], (const float*)d_in[9],
                         (const float*)d_in[11]};
    float* out = (float*)d_out;

    __nv_bfloat16 *ahi, *alo, *whi, *wlo;
    float* tm;
    cudaGetSymbolAddress((void**)&ahi, g_Ahi);
    cudaGetSymbolAddress((void**)&alo, g_Alo);
    cudaGetSymbolAddress((void**)&whi, g_Whi);
    cudaGetSymbolAddress((void**)&wlo, g_Wlo);
    cudaGetSymbolAddress((void**)&tm, g_tmp);

    static int attr_set = 0;
    if (!attr_set) {
        cudaFuncSetAttribute(bgemm_kernel, cudaFuncAttributeMaxDynamicSharedMemorySize, 65536);
        attr_set = 1;
    }

    // graph preprocessing
    detect_idx_kernel<<<1, 1>>>(e);
    zero_deg_kernel<<<(N_NODES + 255) / 256, 256>>>();
    count_deg_kernel<<<(N_EDGES + 255) / 256, 256>>>(e);
    block_sum_kernel<<<GSCAN, 1024>>>();
    scan_partials_kernel<<<1, 1>>>();
    scatter_scan_kernel<<<GSCAN, 1024>>>();
    fill_csr_kernel<<<(N_EDGES + 255) / 256, 256>>>(e);

    const int dims[6] = {512, 2048, 1024, 512, 256, 128};

    // weight conversion + transpose (all layers)
    long long woff[5];
    {
        long long o = 0;
        for (int l = 0; l < 5; l++) {
            woff[l] = o;
            o += (long long)dims[l] * dims[l + 1];
        }
    }
    for (int l = 0; l < 5; l++) {
        int cnt = dims[l] * dims[l + 1];
        convert_w_kernel<<<(cnt + 255) / 256, 256>>>(W[l], woff[l], dims[l], dims[l + 1]);
    }

    // input conversion
    {
        long long n = (long long)N_NODES * 512;
        convert_x_kernel<<<(unsigned)((n + 255) / 256), 256>>>(x, n);
    }

    for (int l = 0; l < 5; l++) {
        int K = dims[l];
        int N = dims[l + 1];
        dim3 grid(N / 128, (N_NODES + 127) / 128);
        bgemm_kernel<<<grid, 256, 65536>>>(ahi, alo, whi + woff[l], wlo + woff[l],
                                           tm, N_NODES, N, K);
        agg_kernel<<<N_NODES, 128>>>(tm, b[l], out, ahi, alo, N, l == 4 ? 1 : 0);
    }
}

// round 6
// speedup vs baseline: 2.8280x; 1.1438x over previous
#include <cuda_runtime.h>
#include <cuda_bf16.h>
#include <cstdint>

#define N_NODES 50000
#define N_EDGES 320000
#define GSCAN   ((N_NODES + 1023) / 1024)

typedef __nv_bfloat16 bf16;

// ---------------- static scratch (no allocations allowed) ----------------
__device__ bf16  g_Ahi[(size_t)N_NODES * 1024];   // activation buffer A (hi)
__device__ bf16  g_Alo[(size_t)N_NODES * 1024];   // activation buffer A (lo)
__device__ bf16  g_Bhi[(size_t)N_NODES * 2048];   // activation buffer B (hi)
__device__ bf16  g_Blo[(size_t)N_NODES * 2048];   // activation buffer B (lo)
__device__ float g_tmp[(size_t)N_NODES * 1024];   // GEMM fp32 out (pre-agg), max d=1024
__device__ bf16  g_Whi[4 * 1024 * 1024];          // transposed weights hi
__device__ bf16  g_Wlo[4 * 1024 * 1024];          // transposed weights lo

__device__ int   g_deg[N_NODES];
__device__ float g_dinv[N_NODES];
__device__ int   g_rowptr[N_NODES + 1];
__device__ int   g_fill[N_NODES];
__device__ int   g_csr[N_EDGES];
__device__ int   g_bsum[64];
__device__ int   g_is64;

// ---------------- index dtype handling ----------------
__global__ void detect_idx_kernel(const void* e) {
    const int* w = (const int*)e;
    int all0 = 1;
    for (int i = 1; i < 64; i += 2)
        if (w[i] != 0) all0 = 0;
    g_is64 = all0;
}

__device__ __forceinline__ int get_idx(const void* e, long long i) {
    if (g_is64) return (int)((const long long*)e)[i];
    return ((const int*)e)[i];
}

// ---------------- graph preprocessing ----------------
__global__ void zero_deg_kernel() {
    int i = blockIdx.x * blockDim.x + threadIdx.x;
    if (i < N_NODES) g_deg[i] = 0;
}

__global__ void count_deg_kernel(const void* e) {
    int i = blockIdx.x * blockDim.x + threadIdx.x;
    if (i >= N_EDGES) return;
    int dst = get_idx(e, (long long)N_EDGES + i);
    atomicAdd(&g_deg[dst], 1);
}

__global__ void block_sum_kernel() {
    int i = blockIdx.x * 1024 + threadIdx.x;
    int v = (i < N_NODES) ? g_deg[i] : 0;
    int lane = threadIdx.x & 31, warp = threadIdx.x >> 5;
#pragma unroll
    for (int off = 16; off > 0; off >>= 1) v += __shfl_down_sync(0xffffffffu, v, off);
    __shared__ int ws[32];
    if (lane == 0) ws[warp] = v;
    __syncthreads();
    if (warp == 0) {
        int s = ws[lane];
#pragma unroll
        for (int off = 16; off > 0; off >>= 1) s += __shfl_down_sync(0xffffffffu, s, off);
        if (lane == 0) g_bsum[blockIdx.x] = s;
    }
}

__global__ void scan_partials_kernel() {
    int acc = 0;
    for (int i = 0; i < GSCAN; i++) { int t = g_bsum[i]; g_bsum[i] = acc; acc += t; }
    g_rowptr[N_NODES] = acc;
}

__global__ void scatter_scan_kernel() {
    int i = blockIdx.x * 1024 + threadIdx.x;
    int v = (i < N_NODES) ? g_deg[i] : 0;
    int lane = threadIdx.x & 31, warp = threadIdx.x >> 5;
    int incl = v;
#pragma unroll
    for (int off = 1; off < 32; off <<= 1) {
        int t = __shfl_up_sync(0xffffffffu, incl, off);
        if (lane >= off) incl += t;
    }
    __shared__ int ws[32];
    if (lane == 31) ws[warp] = incl;
    __syncthreads();
    if (warp == 0) {
        int s = ws[lane];
#pragma unroll
        for (int off = 1; off < 32; off <<= 1) {
            int t = __shfl_up_sync(0xffffffffu, s, off);
            if (lane >= off) s += t;
        }
        ws[lane] = s;
    }
    __syncthreads();
    int wbase = (warp == 0) ? 0 : ws[warp - 1];
    int excl = g_bsum[blockIdx.x] + wbase + incl - v;
    if (i < N_NODES) {
        g_rowptr[i] = excl;
        g_fill[i]   = excl;
        g_dinv[i]   = rsqrtf((float)v + 1.0f);
    }
}

__global__ void fill_csr_kernel(const void* e) {
    int i = blockIdx.x * blockDim.x + threadIdx.x;
    if (i >= N_EDGES) return;
    int src = get_idx(e, i);
    int dst = get_idx(e, (long long)N_EDGES + i);
    int pos = atomicAdd(&g_fill[dst], 1);
    g_csr[pos] = src;
}

// ---------------- weight conversion: W [K,N] -> Wt [N,K] hi/lo ----------------
__global__ void convert_w_kernel(const float* __restrict__ W, long long off, int K, int N) {
    int idx = blockIdx.x * blockDim.x + threadIdx.x;
    if (idx >= K * N) return;
    int k = idx / N, n = idx % N;
    float v = W[idx];
    bf16 h = __float2bfloat16(v);
    g_Whi[off + (size_t)n * K + k] = h;
    g_Wlo[off + (size_t)n * K + k] = __float2bfloat16(v - __bfloat162float(h));
}

// ---------------- bf16-split tensor-core GEMM (mma.sync) ----------------
// C[M,N] = A[M,K] @ Wt[N,K]^T using acc += ahi*bhi + ahi*blo + alo*bhi
// 128x128x32 tiles, 256 threads (8 warps of 64x32), cp.async 2-stage,
// xor-swizzled smem + ldmatrix.x4, mma.sync.m16n8k16 bf16.
// mode 0: store fp32 C.  mode 1: fused bias+relu+bf16 hi/lo split into Ohi/Olo.
__device__ __forceinline__ void ldm4(uint32_t* r, uint32_t addr) {
    asm volatile("ldmatrix.sync.aligned.m8n8.x4.shared.b16 {%0,%1,%2,%3}, [%4];"
                 : "=r"(r[0]), "=r"(r[1]), "=r"(r[2]), "=r"(r[3]) : "r"(addr));
}

__device__ __forceinline__ void mma16816(float* c, const uint32_t* a, const uint32_t* b) {
    asm volatile(
        "mma.sync.aligned.m16n8k16.row.col.f32.bf16.bf16.f32 "
        "{%0,%1,%2,%3},{%4,%5,%6,%7},{%8,%9},{%0,%1,%2,%3};"
        : "+f"(c[0]), "+f"(c[1]), "+f"(c[2]), "+f"(c[3])
        : "r"(a[0]), "r"(a[1]), "r"(a[2]), "r"(a[3]), "r"(b[0]), "r"(b[1]));
}

__device__ __forceinline__ void cp16(uint32_t dst, const void* src, bool pred) {
    int sz = pred ? 16 : 0;
    asm volatile("cp.async.cg.shared.global [%0], [%1], 16, %2;\n"
                 :: "r"(dst), "l"(src), "r"(sz));
}

__device__ __forceinline__ void load_stage(
    uint32_t sbase, int stage,
    const bf16* __restrict__ Ahi, const bf16* __restrict__ Alo,
    const bf16* __restrict__ Bhi, const bf16* __restrict__ Blo,
    int bm, int bn, int k0, int M, int K, int tid)
{
    uint32_t st = sbase + stage * 32768;
#pragma unroll
    for (int h = 0; h < 2; h++) {
        int i = tid + h * 256;
        int row = i >> 2, chunk = i & 3;
        uint32_t doff = (uint32_t)(row * 32 + (chunk ^ ((row >> 1) & 3)) * 8) * 2;
        long arow = bm + row;
        bool av = arow < M;
        long arowc = av ? arow : 0;
        const bf16* pa = Ahi + (size_t)arowc * K + k0 + chunk * 8;
        const bf16* pal = Alo + (size_t)arowc * K + k0 + chunk * 8;
        const bf16* pb = Bhi + (size_t)(bn + row) * K + k0 + chunk * 8;
        const bf16* pbl = Blo + (size_t)(bn + row) * K + k0 + chunk * 8;
        cp16(st + 0 * 8192 + doff, pa, av);
        cp16(st + 1 * 8192 + doff, pal, av);
        cp16(st + 2 * 8192 + doff, pb, true);
        cp16(st + 3 * 8192 + doff, pbl, true);
    }
}

__global__ void __launch_bounds__(256)
bgemm_kernel(const bf16* __restrict__ Ahi, const bf16* __restrict__ Alo,
             const bf16* __restrict__ Bhi, const bf16* __restrict__ Blo,
             float* __restrict__ C, const float* __restrict__ bias,
             bf16* __restrict__ Ohi, bf16* __restrict__ Olo,
             int M, int N, int K, int mode)
{
    extern __shared__ __align__(16) char smem[];
    uint32_t sbase = (uint32_t)__cvta_generic_to_shared(smem);

    int tid  = threadIdx.x;
    int lane = tid & 31, wid = tid >> 5;
    int wm = (wid >> 2) * 64;
    int wn = (wid & 3) * 32;
    int bm = blockIdx.y * 128;
    int bn = blockIdx.x * 128;

    float acc[4][4][4];
#pragma unroll
    for (int i = 0; i < 4; i++)
#pragma unroll
        for (int j = 0; j < 4; j++)
#pragma unroll
            for (int r = 0; r < 4; r++) acc[i][j][r] = 0.f;

    int nk = K >> 5;
    load_stage(sbase, 0, Ahi, Alo, Bhi, Blo, bm, bn, 0, M, K, tid);
    asm volatile("cp.async.commit_group;\n");

    int lr = lane & 15, lc = lane >> 4;

    for (int kt = 0; kt < nk; kt++) {
        if (kt + 1 < nk) {
            load_stage(sbase, (kt + 1) & 1, Ahi, Alo, Bhi, Blo, bm, bn, (kt + 1) * 32, M, K, tid);
            asm volatile("cp.async.commit_group;\n");
            asm volatile("cp.async.wait_group 1;\n");
        } else {
            asm volatile("cp.async.wait_group 0;\n");
        }
        __syncthreads();

        uint32_t st = sbase + (kt & 1) * 32768;
#pragma unroll
        for (int kk = 0; kk < 32; kk += 16) {
            int k = kk + lc * 8;
            uint32_t ah[4][4], al[4][4], bh[4][2], bl[4][2];
#pragma unroll
            for (int fm = 0; fm < 4; fm++) {
                int row = wm + fm * 16 + lr;
                uint32_t off = (uint32_t)(row * 32 + (((k >> 3) ^ ((row >> 1) & 3)) << 3)) * 2;
                ldm4(ah[fm], st + 0 * 8192 + off);
                ldm4(al[fm], st + 1 * 8192 + off);
            }
#pragma unroll
            for (int p = 0; p < 2; p++) {
                int row = wn + p * 16 + lr;
                uint32_t off = (uint32_t)(row * 32 + (((k >> 3) ^ ((row >> 1) & 3)) << 3)) * 2;
                uint32_t r[4];
                ldm4(r, st + 2 * 8192 + off);
                bh[p * 2][0] = r[0]; bh[p * 2][1] = r[2];
                bh[p * 2 + 1][0] = r[1]; bh[p * 2 + 1][1] = r[3];
                ldm4(r, st + 3 * 8192 + off);
                bl[p * 2][0] = r[0]; bl[p * 2][1] = r[2];
                bl[p * 2 + 1][0] = r[1]; bl[p * 2 + 1][1] = r[3];
            }
#pragma unroll
            for (int fm = 0; fm < 4; fm++)
#pragma unroll
                for (int fn = 0; fn < 4; fn++) {
                    mma16816(acc[fm][fn], ah[fm], bh[fn]);
                    mma16816(acc[fm][fn], ah[fm], bl[fn]);
                    mma16816(acc[fm][fn], al[fm], bh[fn]);
                }
        }
        __syncthreads();
    }

    int g = lane >> 2, tg = lane & 3;
    if (mode == 0) {
#pragma unroll
        for (int fm = 0; fm < 4; fm++) {
#pragma unroll
            for (int fn = 0; fn < 4; fn++) {
                int row = bm + wm + fm * 16 + g;
                int col = bn + wn + fn * 8 + tg * 2;
                if (row < M)
                    *(float2*)&C[(size_t)row * N + col] = make_float2(acc[fm][fn][0], acc[fm][fn][1]);
                if (row + 8 < M)
                    *(float2*)&C[(size_t)(row + 8) * N + col] = make_float2(acc[fm][fn][2], acc[fm][fn][3]);
            }
        }
    } else {
#pragma unroll
        for (int fm = 0; fm < 4; fm++) {
#pragma unroll
            for (int fn = 0; fn < 4; fn++) {
                int col = bn + wn + fn * 8 + tg * 2;
                float2 bv = *(const float2*)&bias[col];
#pragma unroll
                for (int h = 0; h < 2; h++) {
                    int row = bm + wm + fm * 16 + g + h * 8;
                    if (row >= M) continue;
                    float v0 = fmaxf(acc[fm][fn][h * 2]     + bv.x, 0.f);
                    float v1 = fmaxf(acc[fm][fn][h * 2 + 1] + bv.y, 0.f);
                    bf16 h0 = __float2bfloat16(v0);
                    bf16 h1 = __float2bfloat16(v1);
                    __nv_bfloat162 hh; hh.x = h0; hh.y = h1;
                    *(__nv_bfloat162*)&Ohi[(size_t)row * N + col] = hh;
                    __nv_bfloat162 ll;
                    ll.x = __float2bfloat16(v0 - __bfloat162float(h0));
                    ll.y = __float2bfloat16(v1 - __bfloat162float(h1));
                    *(__nv_bfloat162*)&Olo[(size_t)row * N + col] = ll;
                }
            }
        }
    }
}

// ---------------- aggregation of raw input x (d=512, fp32) -> bf16 hi/lo ----------------
__global__ void __launch_bounds__(128)
aggx_kernel(const float* __restrict__ x, bf16* __restrict__ ohi, bf16* __restrict__ olo)
{
    const int d = 512;
    int node = blockIdx.x;
    int tid  = threadIdx.x;
    float di = g_dinv[node];
    int beg = g_rowptr[node];
    int end = g_rowptr[node + 1];

    float selfn = di * di;
    float4 v = ((const float4*)(x + (size_t)node * d))[tid];
    float4 acc = make_float4(v.x * selfn, v.y * selfn, v.z * selfn, v.w * selfn);

    for (int e = beg; e < end; e++) {
        int src = g_csr[e];
        float nrm = di * g_dinv[src];
        float4 w = ((const float4*)(x + (size_t)src * d))[tid];
        acc.x += w.x * nrm; acc.y += w.y * nrm;
        acc.z += w.z * nrm; acc.w += w.w * nrm;
    }

    bf16 h0 = __float2bfloat16(acc.x), h1 = __float2bfloat16(acc.y);
    bf16 h2 = __float2bfloat16(acc.z), h3 = __float2bfloat16(acc.w);
    __nv_bfloat162 hh01; hh01.x = h0; hh01.y = h1;
    __nv_bfloat162 hh23; hh23.x = h2; hh23.y = h3;
    ((__nv_bfloat162*)(ohi + (size_t)node * d))[2 * tid]     = hh01;
    ((__nv_bfloat162*)(ohi + (size_t)node * d))[2 * tid + 1] = hh23;
    __nv_bfloat162 ll01, ll23;
    ll01.x = __float2bfloat16(acc.x - __bfloat162float(h0));
    ll01.y = __float2bfloat16(acc.y - __bfloat162float(h1));
    ll23.x = __float2bfloat16(acc.z - __bfloat162float(h2));
    ll23.y = __float2bfloat16(acc.w - __bfloat162float(h3));
    ((__nv_bfloat162*)(olo + (size_t)node * d))[2 * tid]     = ll01;
    ((__nv_bfloat162*)(olo + (size_t)node * d))[2 * tid + 1] = ll23;
}

// ---------------- CSR aggregation, wide (d = 512 or 1024), block per node --------
__global__ void __launch_bounds__(128)
agg_wide_kernel(const float* __restrict__ tmp, const float* __restrict__ bias,
                bf16* __restrict__ ohi, bf16* __restrict__ olo, int d)
{
    int node = blockIdx.x;
    int tid  = threadIdx.x;
    float di = g_dinv[node];
    int beg = g_rowptr[node];
    int end = g_rowptr[node + 1];
    int nc4 = d >> 2;

    float4 acc[2];
    float selfn = di * di;
    const float4* selfrow = (const float4*)(tmp + (size_t)node * d);
#pragma unroll
    for (int j = 0; j < 2; j++) {
        int c = tid + j * 128;
        if (c < nc4) {
            float4 v = selfrow[c];
            acc[j] = make_float4(v.x * selfn, v.y * selfn, v.z * selfn, v.w * selfn);
        } else acc[j] = make_float4(0.f, 0.f, 0.f, 0.f);
    }

    for (int e = beg; e < end; e++) {
        int src = g_csr[e];
        float nrm = di * g_dinv[src];
        const float4* row = (const float4*)(tmp + (size_t)src * d);
#pragma unroll
        for (int j = 0; j < 2; j++) {
            int c = tid + j * 128;
            if (c < nc4) {
                float4 v = row[c];
                acc[j].x += v.x * nrm; acc[j].y += v.y * nrm;
                acc[j].z += v.z * nrm; acc[j].w += v.w * nrm;
            }
        }
    }

    const float4* b4 = (const float4*)bias;
#pragma unroll
    for (int j = 0; j < 2; j++) {
        int c = tid + j * 128;
        if (c >= nc4) continue;
        float4 bv = b4[c];
        float4 r = make_float4(fmaxf(acc[j].x + bv.x, 0.f), fmaxf(acc[j].y + bv.y, 0.f),
                               fmaxf(acc[j].z + bv.z, 0.f), fmaxf(acc[j].w + bv.w, 0.f));
        bf16 h0 = __float2bfloat16(r.x), h1 = __float2bfloat16(r.y);
        bf16 h2 = __float2bfloat16(r.z), h3 = __float2bfloat16(r.w);
        __nv_bfloat162 hh01; hh01.x = h0; hh01.y = h1;
        __nv_bfloat162 hh23; hh23.x = h2; hh23.y = h3;
        ((__nv_bfloat162*)(ohi + (size_t)node * d))[2 * c]     = hh01;
        ((__nv_bfloat162*)(ohi + (size_t)node * d))[2 * c + 1] = hh23;
        __nv_bfloat162 ll01, ll23;
        ll01.x = __float2bfloat16(r.x - __bfloat162float(h0));
        ll01.y = __float2bfloat16(r.y - __bfloat162float(h1));
        ll23.x = __float2bfloat16(r.z - __bfloat162float(h2));
        ll23.y = __float2bfloat16(r.w - __bfloat162float(h3));
        ((__nv_bfloat162*)(olo + (size_t)node * d))[2 * c]     = ll01;
        ((__nv_bfloat162*)(olo + (size_t)node * d))[2 * c + 1] = ll23;
    }
}

// ---------------- CSR aggregation, narrow (d = 128 or 256), warp per node --------
__global__ void __launch_bounds__(128)
agg_narrow_kernel(const float* __restrict__ tmp, const float* __restrict__ bias,
                  float* __restrict__ outf, bf16* __restrict__ ohi,
                  bf16* __restrict__ olo, int d, int last)
{
    int node = blockIdx.x * 4 + (threadIdx.x >> 5);
    if (node >= N_NODES) return;
    int lane = threadIdx.x & 31;
    int nc4 = d >> 2;   // 32 or 64
    float di = g_dinv[node];
    int beg = g_rowptr[node];
    int end = g_rowptr[node + 1];

    float4 acc[2];
    float selfn = di * di;
    const float4* selfrow = (const float4*)(tmp + (size_t)node * d);
#pragma unroll
    for (int j = 0; j < 2; j++) {
        int c = lane + j * 32;
        if (c < nc4) {
            float4 v = selfrow[c];
            acc[j] = make_float4(v.x * selfn, v.y * selfn, v.z * selfn, v.w * selfn);
        } else acc[j] = make_float4(0.f, 0.f, 0.f, 0.f);
    }

    for (int e = beg; e < end; e++) {
        int src = g_csr[e];
        float nrm = di * g_dinv[src];
        const float4* row = (const float4*)(tmp + (size_t)src * d);
#pragma unroll
        for (int j = 0; j < 2; j++) {
            int c = lane + j * 32;
            if (c < nc4) {
                float4 v = row[c];
                acc[j].x += v.x * nrm; acc[j].y += v.y * nrm;
                acc[j].z += v.z * nrm; acc[j].w += v.w * nrm;
            }
        }
    }

    const float4* b4 = (const float4*)bias;
#pragma unroll
    for (int j = 0; j < 2; j++) {
        int c = lane + j * 32;
        if (c >= nc4) continue;
        float4 bv = b4[c];
        float4 r = make_float4(acc[j].x + bv.x, acc[j].y + bv.y,
                               acc[j].z + bv.z, acc[j].w + bv.w);
        if (last) {
            ((float4*)(outf + (size_t)node * d))[c] = r;
        } else {
            r.x = fmaxf(r.x, 0.f); r.y = fmaxf(r.y, 0.f);
            r.z = fmaxf(r.z, 0.f); r.w = fmaxf(r.w, 0.f);
            bf16 h0 = __float2bfloat16(r.x), h1 = __float2bfloat16(r.y);
            bf16 h2 = __float2bfloat16(r.z), h3 = __float2bfloat16(r.w);
            __nv_bfloat162 hh01; hh01.x = h0; hh01.y = h1;
            __nv_bfloat162 hh23; hh23.x = h2; hh23.y = h3;
            ((__nv_bfloat162*)(ohi + (size_t)node * d))[2 * c]     = hh01;
            ((__nv_bfloat162*)(ohi + (size_t)node * d))[2 * c + 1] = hh23;
            __nv_bfloat162 ll01, ll23;
            ll01.x = __float2bfloat16(r.x - __bfloat162float(h0));
            ll01.y = __float2bfloat16(r.y - __bfloat162float(h1));
            ll23.x = __float2bfloat16(r.z - __bfloat162float(h2));
            ll23.y = __float2bfloat16(r.w - __bfloat162float(h3));
            ((__nv_bfloat162*)(olo + (size_t)node * d))[2 * c]     = ll01;
            ((__nv_bfloat162*)(olo + (size_t)node * d))[2 * c + 1] = ll23;
        }
    }
}

// ---------------- launch ----------------
extern "C" void kernel_launch(void* const* d_in, const int* in_sizes, int n_in,
                              void* d_out, int out_size) {
    const float* x = (const float*)d_in[0];
    const void*  e = d_in[1];
    const float* W[5] = {(const float*)d_in[2], (const float*)d_in[4],
                         (const float*)d_in[6], (const float*)d_in[8],
                         (const float*)d_in[10]};
    const float* b[5] = {(const float*)d_in[3], (const float*)d_in[5],
                         (const float*)d_in[7], (const float*)d_in[9],
                         (const float*)d_in[11]};
    float* out = (float*)d_out;

    bf16 *ahi, *alo, *bhi, *blo, *whi, *wlo;
    float* tm;
    cudaGetSymbolAddress((void**)&ahi, g_Ahi);
    cudaGetSymbolAddress((void**)&alo, g_Alo);
    cudaGetSymbolAddress((void**)&bhi, g_Bhi);
    cudaGetSymbolAddress((void**)&blo, g_Blo);
    cudaGetSymbolAddress((void**)&whi, g_Whi);
    cudaGetSymbolAddress((void**)&wlo, g_Wlo);
    cudaGetSymbolAddress((void**)&tm, g_tmp);

    static int attr_set = 0;
    if (!attr_set) {
        cudaFuncSetAttribute(bgemm_kernel, cudaFuncAttributeMaxDynamicSharedMemorySize, 65536);
        attr_set = 1;
    }

    // graph preprocessing
    detect_idx_kernel<<<1, 1>>>(e);
    zero_deg_kernel<<<(N_NODES + 255) / 256, 256>>>();
    count_deg_kernel<<<(N_EDGES + 255) / 256, 256>>>(e);
    block_sum_kernel<<<GSCAN, 1024>>>();
    scan_partials_kernel<<<1, 1>>>();
    scatter_scan_kernel<<<GSCAN, 1024>>>();
    fill_csr_kernel<<<(N_EDGES + 255) / 256, 256>>>(e);

    const int dims[6] = {512, 2048, 1024, 512, 256, 128};
    long long woff[5];
    {
        long long o = 0;
        for (int l = 0; l < 5; l++) { woff[l] = o; o += (long long)dims[l] * dims[l + 1]; }
    }
    for (int l = 0; l < 5; l++) {
        int cnt = dims[l] * dims[l + 1];
        convert_w_kernel<<<(cnt + 255) / 256, 256>>>(W[l], woff[l], dims[l], dims[l + 1]);
    }

    int gy = (N_NODES + 127) / 128;

    // L1: aggregate x first (d=512, linearity), then GEMM with fused
    //     bias+relu+hi/lo epilogue straight into buffer B (2048-wide).
    aggx_kernel<<<N_NODES, 128>>>(x, ahi, alo);
    {
        dim3 grid(2048 / 128, gy);
        bgemm_kernel<<<grid, 256, 65536>>>(ahi, alo, whi + woff[0], wlo + woff[0],
                                           nullptr, b[0], bhi, blo,
                                           N_NODES, 2048, 512, 1);
    }

    // L2..L5: GEMM -> tmp fp32 -> aggregate (+bias, +relu/split or final fp32)
    bf16* inhi[4] = {bhi, ahi, bhi, ahi};
    bf16* inlo[4] = {blo, alo, blo, alo};
    bf16* othi[4] = {ahi, bhi, ahi, nullptr};
    bf16* otlo[4] = {alo, blo, alo, nullptr};
    for (int l = 1; l < 5; l++) {
        int K = dims[l], N = dims[l + 1];
        dim3 grid(N / 128, gy);
        bgemm_kernel<<<grid, 256, 65536>>>(inhi[l - 1], inlo[l - 1],
                                           whi + woff[l], wlo + woff[l],
                                           tm, nullptr, nullptr, nullptr,
                                           N_NODES, N, K, 0);
        if (N >= 512) {
            agg_wide_kernel<<<N_NODES, 128>>>(tm, b[l], othi[l - 1], otlo[l - 1], N);
        } else {
            agg_narrow_kernel<<<(N_NODES + 3) / 4, 128>>>(tm, b[l], out,
                                                          othi[l - 1], otlo[l - 1],
                                                          N, l == 4 ? 1 : 0);
        }
    }
}